// round 2
// baseline (speedup 1.0000x reference)
#include <cuda_runtime.h>
#include <cuda_bf16.h>
#include <math.h>

// Problem constants (fixed by setup_inputs)
#define BATCH 32
#define SEQ   256
#define HID   768

// GEMM tiling
#define BM 128
#define BN 256
#define BK 16
#define NTHREADS 512

// Scratch (allocation-free rule: __device__ globals)
__device__ float g_qn[BATCH * SEQ * HID];
__device__ float g_kn[BATCH * SEQ * HID];
__device__ float g_wd[SEQ];        // scale * exp(-alpha * d)
__device__ float g_invden[BATCH];  // 1 / clip(sum q_mask, 1, inf)
__device__ float g_partial[BATCH * BATCH * 2];

#define NEG_HUGE (-3.402823466e38f)

// ---------------------------------------------------------------------------
// Kernel 1: L2-normalize every token of Q and K.
// grid = 2*BATCH*SEQ blocks of 256 threads, one row (768 elems) per block.
// ---------------------------------------------------------------------------
__global__ void norm_kernel(const float* __restrict__ q,
                            const float* __restrict__ k) {
    int row = blockIdx.x;
    const float* src;
    float* dst;
    if (row < BATCH * SEQ) {
        src = q + (size_t)row * HID;
        dst = g_qn + (size_t)row * HID;
    } else {
        int r = row - BATCH * SEQ;
        src = k + (size_t)r * HID;
        dst = g_kn + (size_t)r * HID;
    }
    int t = threadIdx.x;  // 256 threads, 3 elems each
    float v0 = src[t];
    float v1 = src[t + 256];
    float v2 = src[t + 512];
    float ss = v0 * v0 + v1 * v1 + v2 * v2;
#pragma unroll
    for (int o = 16; o > 0; o >>= 1) ss += __shfl_xor_sync(0xFFFFFFFFu, ss, o);

    __shared__ float sred[8];
    __shared__ float s_inv;
    if ((t & 31) == 0) sred[t >> 5] = ss;
    __syncthreads();
    if (t == 0) {
        float tot = 0.f;
#pragma unroll
        for (int w = 0; w < 8; w++) tot += sred[w];
        s_inv = 1.0f / fmaxf(sqrtf(tot), 1e-12f);
    }
    __syncthreads();
    float inv = s_inv;
    dst[t]       = v0 * inv;
    dst[t + 256] = v1 * inv;
    dst[t + 512] = v2 * inv;
}

// ---------------------------------------------------------------------------
// Kernel 2: tiny tables — decay weights (with logit scale folded in) and
// per-query-batch inverse denominators.  1 block, 256 threads.
// ---------------------------------------------------------------------------
__global__ void tables_kernel(const float* __restrict__ qmask,
                              const float* __restrict__ alpha_raw,
                              const float* __restrict__ logit_scale) {
    int t = threadIdx.x;
    float a = *alpha_raw;
    float alpha = (a > 20.f) ? a : log1pf(expf(a));   // softplus
    float scale = expf(*logit_scale);
    g_wd[t] = scale * expf(-alpha * (float)t);
    if (t < BATCH) {
        float s = 0.f;
        for (int x = 0; x < SEQ; x++) s += qmask[t * SEQ + x];
        g_invden[t] = 1.0f / fmaxf(s, 1.0f);
    }
}

// ---------------------------------------------------------------------------
// Kernel 3: main fused kernel.
// One block per (pair, s-half): sim0 tile (128 x 256) over K=768 in registers,
// then fused decay + masked softmax + score = sum_t p*sim0, reduced to one
// partial per block.  score never touches global memory.
//
// Thread layout: 512 threads = 16 warps. Warp w owns s-rows [8w, 8w+8).
// Lane l owns t-cols {4l..4l+3} U {128+4l..128+4l+3}  (two contiguous float4
// groups -> conflict-free LDS.128; A fragment is warp-broadcast).
// ---------------------------------------------------------------------------
__global__ __launch_bounds__(NTHREADS, 1)
void pair_kernel(const float* __restrict__ qmask,
                 const float* __restrict__ kmask) {
    __shared__ float As[BK][BM + 4];   // 16 x 132
    __shared__ float Bs[BK][BN + 4];   // 16 x 260
    __shared__ float s_wd[SEQ];
    __shared__ float s_kv[SEQ];
    __shared__ float s_red[16];

    const int bx    = blockIdx.x;
    const int pair  = bx >> 1;
    const int chunk = bx & 1;
    const int i = pair >> 5;
    const int j = pair & 31;
    const int s0 = chunk * BM;

    const int tid  = threadIdx.x;
    const int warp = tid >> 5;
    const int lane = tid & 31;

    const float* Ag = g_qn + ((size_t)i * SEQ + s0) * HID;  // 128 x 768
    const float* Bg = g_kn + ((size_t)j * SEQ) * HID;       // 256 x 768

    if (tid < SEQ) {
        s_wd[tid] = g_wd[tid];
        s_kv[tid] = (kmask[j * SEQ + tid] > 0.f) ? 1.f : 0.f;
    }

    float acc[8][8];
#pragma unroll
    for (int r = 0; r < 8; r++)
#pragma unroll
        for (int c = 0; c < 8; c++) acc[r][c] = 0.f;

    // Global->smem load mapping
    const int am = tid >> 2;            // 0..127
    const int ak = (tid & 3) * 4;       // {0,4,8,12}
    const int bn = tid >> 1;            // 0..255
    const int bq0 = (tid & 1) * 2;      // {0,2}: two float4 per thread

    for (int k0 = 0; k0 < HID; k0 += BK) {
        // prefetch from global (L2-resident after first wave)
        float4 av  = *(const float4*)(Ag + (size_t)am * HID + k0 + ak);
        float4 bv0 = *(const float4*)(Bg + (size_t)bn * HID + k0 + bq0 * 4);
        float4 bv1 = *(const float4*)(Bg + (size_t)bn * HID + k0 + bq0 * 4 + 4);
        __syncthreads();   // previous tile fully consumed
        As[ak + 0][am] = av.x;
        As[ak + 1][am] = av.y;
        As[ak + 2][am] = av.z;
        As[ak + 3][am] = av.w;
        Bs[bq0 * 4 + 0][bn] = bv0.x;
        Bs[bq0 * 4 + 1][bn] = bv0.y;
        Bs[bq0 * 4 + 2][bn] = bv0.z;
        Bs[bq0 * 4 + 3][bn] = bv0.w;
        Bs[bq0 * 4 + 4][bn] = bv1.x;
        Bs[bq0 * 4 + 5][bn] = bv1.y;
        Bs[bq0 * 4 + 6][bn] = bv1.z;
        Bs[bq0 * 4 + 7][bn] = bv1.w;
        __syncthreads();

#pragma unroll
        for (int kk = 0; kk < BK; kk++) {
            float4 a0 = *(const float4*)&As[kk][warp * 8];
            float4 a1 = *(const float4*)&As[kk][warp * 8 + 4];
            float4 b0 = *(const float4*)&Bs[kk][lane * 4];
            float4 b1 = *(const float4*)&Bs[kk][128 + lane * 4];
            float a[8] = {a0.x, a0.y, a0.z, a0.w, a1.x, a1.y, a1.z, a1.w};
            float b[8] = {b0.x, b0.y, b0.z, b0.w, b1.x, b1.y, b1.z, b1.w};
#pragma unroll
            for (int r = 0; r < 8; r++)
#pragma unroll
                for (int c = 0; c < 8; c++)
                    acc[r][c] = fmaf(a[r], b[c], acc[r][c]);
        }
    }

    // ---- fused decay + masked softmax + score, per s-row -----------------
    float rowsum = 0.f;
#pragma unroll
    for (int r = 0; r < 8; r++) {
        const int s = s0 + warp * 8 + r;
        const float qmv = qmask[i * SEQ + s];
        const int qvalid = (qmv > 0.f) ? 1 : 0;

        float lg[8];
        float lmax = NEG_HUGE;
#pragma unroll
        for (int c = 0; c < 8; c++) {
            int t = (c < 4) ? (lane * 4 + c) : (128 + lane * 4 + (c - 4));
            int d = s - t; if (d < 0) d = -d;
            float l = acc[r][c] * s_wd[d];
            lg[c] = l;
            if (qvalid && s_kv[t] > 0.f) lmax = fmaxf(lmax, l);
        }
#pragma unroll
        for (int o = 16; o > 0; o >>= 1)
            lmax = fmaxf(lmax, __shfl_xor_sync(0xFFFFFFFFu, lmax, o));

        float sZ = 0.f, sS = 0.f;
#pragma unroll
        for (int c = 0; c < 8; c++) {
            int t = (c < 4) ? (lane * 4 + c) : (128 + lane * 4 + (c - 4));
            float e = (qvalid && s_kv[t] > 0.f) ? __expf(lg[c] - lmax) : 0.f;
            sZ += e;
            sS += e * acc[r][c];
        }
#pragma unroll
        for (int o = 16; o > 0; o >>= 1) {
            sZ += __shfl_xor_sync(0xFFFFFFFFu, sZ, o);
            sS += __shfl_xor_sync(0xFFFFFFFFu, sS, o);
        }
        float sc = (sZ > 0.f) ? (sS / sZ) : 0.f;
        rowsum += sc * qmv;
    }

    if (lane == 0) s_red[warp] = rowsum;
    __syncthreads();
    if (tid == 0) {
        float tot = 0.f;
#pragma unroll
        for (int w = 0; w < 16; w++) tot += s_red[w];
        g_partial[bx] = tot;
    }
}

// ---------------------------------------------------------------------------
// Kernel 4: combine the two s-half partials and apply 1/denom.
// ---------------------------------------------------------------------------
__global__ void finalize_kernel(float* __restrict__ out) {
    int p = blockIdx.x * blockDim.x + threadIdx.x;
    if (p < BATCH * BATCH) {
        out[p] = (g_partial[2 * p] + g_partial[2 * p + 1]) * g_invden[p >> 5];
    }
}

// ---------------------------------------------------------------------------
extern "C" void kernel_launch(void* const* d_in, const int* in_sizes, int n_in,
                              void* d_out, int out_size) {
    const float* q  = (const float*)d_in[0];
    const float* k  = (const float*)d_in[1];
    const float* qm = (const float*)d_in[2];
    const float* km = (const float*)d_in[3];
    const float* ar = (const float*)d_in[4];
    const float* ls = (const float*)d_in[5];
    float* out = (float*)d_out;

    norm_kernel<<<2 * BATCH * SEQ, 256>>>(q, k);
    tables_kernel<<<1, 256>>>(qm, ar, ls);
    pair_kernel<<<BATCH * BATCH * 2, NTHREADS>>>(qm, km);
    finalize_kernel<<<4, 256>>>(out);
}

// round 6
// speedup vs baseline: 1.5872x; 1.5872x over previous
#include <cuda_runtime.h>
#include <cuda_bf16.h>
#include <math.h>
#include <cstdint>

// Problem constants (fixed by setup_inputs)
#define BATCH 32
#define SEQ   256
#define HID   768

#define NTP 512                 // threads per pair block (16 warps, 4x4)
#define KC 32                   // K elems per chunk
#define NCH (HID / KC)          // 24 chunks per pass-phase
#define ROWB 80                 // smem row stride bytes (64B data + 16B pad)

// smem layout (dynamic)
#define SM_WD    0              // 256 floats
#define SM_KV    1024           // 256 floats
#define SM_RED   2048           // 16 floats
#define SM_TILES 4096
#define OFF_AH   0              // 128 rows * 80B = 10240
#define OFF_AL   10240          // 10240
#define OFF_B    20480          // 256 rows * 80B = 20480
#define BUFSZ    40960
#define SMEM_TOTAL (SM_TILES + 2 * BUFSZ)   // 86016

#define NEG_HUGE (-3.402823466e38f)

// Scratch (allocation-free rule: __device__ globals)
__device__ __nv_bfloat16 g_qh[BATCH * SEQ * HID];
__device__ __nv_bfloat16 g_ql[BATCH * SEQ * HID];
__device__ __nv_bfloat16 g_kh[BATCH * SEQ * HID];
__device__ __nv_bfloat16 g_kl[BATCH * SEQ * HID];
__device__ float g_wd[SEQ];
__device__ float g_invden[BATCH];
__device__ float g_partial[BATCH * BATCH * 2];

__device__ __forceinline__ uint32_t smem_u32(const void* p) {
    uint32_t a;
    asm("{ .reg .u64 t; cvta.to.shared.u64 t, %1; cvt.u32.u64 %0, t; }" : "=r"(a) : "l"(p));
    return a;
}

#define LDSM4(A, addr)                                                          \
    asm volatile("ldmatrix.sync.aligned.m8n8.x4.shared.b16 {%0,%1,%2,%3}, [%4];"\
        : "=r"((A)[0]), "=r"((A)[1]), "=r"((A)[2]), "=r"((A)[3]) : "r"(addr))

#define MMA16(acc, A, b0, b1)                                                   \
    asm volatile("mma.sync.aligned.m16n8k16.row.col.f32.bf16.bf16.f32 "         \
        "{%0,%1,%2,%3}, {%4,%5,%6,%7}, {%8,%9}, {%0,%1,%2,%3};"                 \
        : "+f"((acc)[0]), "+f"((acc)[1]), "+f"((acc)[2]), "+f"((acc)[3])        \
        : "r"((A)[0]), "r"((A)[1]), "r"((A)[2]), "r"((A)[3]), "r"(b0), "r"(b1))

// ---------------------------------------------------------------------------
// Kernel 1: L2-normalize, split fp32 -> bf16 hi + bf16 lo residual.
// ---------------------------------------------------------------------------
__global__ void norm_kernel(const float* __restrict__ q,
                            const float* __restrict__ k) {
    int row = blockIdx.x;
    const float* src;
    __nv_bfloat16 *dh, *dl;
    if (row < BATCH * SEQ) {
        src = q + (size_t)row * HID;
        dh = g_qh + (size_t)row * HID; dl = g_ql + (size_t)row * HID;
    } else {
        int r = row - BATCH * SEQ;
        src = k + (size_t)r * HID;
        dh = g_kh + (size_t)r * HID; dl = g_kl + (size_t)r * HID;
    }
    int t = threadIdx.x;
    float v0 = src[t], v1 = src[t + 256], v2 = src[t + 512];
    float ss = v0 * v0 + v1 * v1 + v2 * v2;
#pragma unroll
    for (int o = 16; o > 0; o >>= 1) ss += __shfl_xor_sync(0xFFFFFFFFu, ss, o);
    __shared__ float sred[8];
    __shared__ float s_inv;
    if ((t & 31) == 0) sred[t >> 5] = ss;
    __syncthreads();
    if (t == 0) {
        float tot = 0.f;
#pragma unroll
        for (int w = 0; w < 8; w++) tot += sred[w];
        s_inv = 1.0f / fmaxf(sqrtf(tot), 1e-12f);
    }
    __syncthreads();
    float inv = s_inv;
#pragma unroll
    for (int e = 0; e < 3; e++) {
        float v = (e == 0 ? v0 : (e == 1 ? v1 : v2)) * inv;
        __nv_bfloat16 h = __float2bfloat16(v);
        __nv_bfloat16 l = __float2bfloat16(v - __bfloat162float(h));
        dh[t + e * 256] = h;
        dl[t + e * 256] = l;
    }
}

// ---------------------------------------------------------------------------
// Kernel 2: tiny tables
// ---------------------------------------------------------------------------
__global__ void tables_kernel(const float* __restrict__ qmask,
                              const float* __restrict__ alpha_raw,
                              const float* __restrict__ logit_scale) {
    int t = threadIdx.x;
    float a = *alpha_raw;
    float alpha = (a > 20.f) ? a : log1pf(expf(a));
    float scale = expf(*logit_scale);
    g_wd[t] = scale * expf(-alpha * (float)t);
    if (t < BATCH) {
        float s = 0.f;
        for (int x = 0; x < SEQ; x++) s += qmask[t * SEQ + x];
        g_invden[t] = 1.0f / fmaxf(s, 1.0f);
    }
}

// ---------------------------------------------------------------------------
// Kernel 3: per-(pair, s-half) bf16x3 warp-MMA GEMM (128x256xK768x3passes)
// with fused decay + masked softmax epilogue.
// 16 warps = 4 warp-rows x 4 warp-cols; warp tile 32(s) x 64(t).
// ---------------------------------------------------------------------------
__global__ __launch_bounds__(NTP, 1)
void pair_kernel(const float* __restrict__ qmask,
                 const float* __restrict__ kmask) {
    extern __shared__ char smem[];
    const uint32_t sb = smem_u32(smem);
    float* s_wd = (float*)(smem + SM_WD);
    float* s_kv = (float*)(smem + SM_KV);
    float* s_red = (float*)(smem + SM_RED);

    const int tid = threadIdx.x;
    const int w = tid >> 5, lane = tid & 31;
    const int wr = w >> 2, wc = w & 3;          // warp row/col in 4x4
    const int bx = blockIdx.x;
    const int pair = bx >> 1, half = bx & 1;
    const int i = pair >> 5, j = pair & 31;
    const int s0 = half * 128;

    const __nv_bfloat16* Ah_g = g_qh + ((size_t)i * SEQ + s0) * HID;
    const __nv_bfloat16* Al_g = g_ql + ((size_t)i * SEQ + s0) * HID;
    const __nv_bfloat16* Bh_g = g_kh + (size_t)j * SEQ * HID;
    const __nv_bfloat16* Bl_g = g_kl + (size_t)j * SEQ * HID;

    if (tid < SEQ) {
        s_wd[tid] = g_wd[tid];
        s_kv[tid] = (kmask[j * SEQ + tid] > 0.f) ? 1.f : 0.f;
    }

    float acc[2][8][4];
#pragma unroll
    for (int mi = 0; mi < 2; mi++)
#pragma unroll
        for (int ni = 0; ni < 8; ni++)
#pragma unroll
            for (int e = 0; e < 4; e++) acc[mi][ni][e] = 0.f;

    // LDG->STS mapping: A: tid -> row=tid/4 (0..127), kc8=tid%4 (16B group)
    //                   B: idx=q*512+tid -> row=idx/4 (0..255)
    const int arow = tid >> 2, akc = tid & 3;

    uint4 rah, ral, rb0, rb1;
    bool ral_valid = false;

    // total 48 chunk-iterations: cc<24 = phase1 (Ah,Al x Bh), cc>=24 = phase2 (Ah x Bl)
    auto do_ldg = [&](int cc) {
        int kcol = (cc % NCH) * KC;
        bool p1 = (cc < NCH);
        const __nv_bfloat16* Bg = p1 ? Bh_g : Bl_g;
        rah = *(const uint4*)(Ah_g + (size_t)arow * HID + kcol + akc * 8);
        if (p1) { ral = *(const uint4*)(Al_g + (size_t)arow * HID + kcol + akc * 8); ral_valid = true; }
        else ral_valid = false;
        {
            int idx0 = tid, idx1 = 512 + tid;
            rb0 = *(const uint4*)(Bg + (size_t)(idx0 >> 2) * HID + kcol + (idx0 & 3) * 8);
            rb1 = *(const uint4*)(Bg + (size_t)(idx1 >> 2) * HID + kcol + (idx1 & 3) * 8);
        }
    };
    auto do_sts = [&](int buf) {
        char* tb = smem + SM_TILES + buf * BUFSZ;
        *(uint4*)(tb + OFF_AH + arow * ROWB + akc * 16) = rah;
        if (ral_valid) *(uint4*)(tb + OFF_AL + arow * ROWB + akc * 16) = ral;
        int idx0 = tid, idx1 = 512 + tid;
        *(uint4*)(tb + OFF_B + (idx0 >> 2) * ROWB + (idx0 & 3) * 16) = rb0;
        *(uint4*)(tb + OFF_B + (idx1 >> 2) * ROWB + (idx1 & 3) * 16) = rb1;
    };

    do_ldg(0);
    do_sts(0);
    __syncthreads();

    const uint32_t lrow = lane & 15, lk16 = (lane >> 4) * 16;
    const uint32_t bln = (lane >> 2), blc = (lane & 3) * 4;

    for (int cc = 0; cc < 2 * NCH; cc++) {
        if (cc + 1 < 2 * NCH) do_ldg(cc + 1);
        const int buf = cc & 1;
        const bool p1 = (cc < NCH);
        const uint32_t tb = sb + SM_TILES + buf * BUFSZ;

#pragma unroll
        for (int k16 = 0; k16 < 2; k16++) {
            uint32_t ah[2][4], al[2][4];
            uint32_t koff = k16 * 32 + lk16;
#pragma unroll
            for (int mi = 0; mi < 2; mi++) {
                uint32_t row = wr * 32 + mi * 16 + lrow;
                LDSM4(ah[mi], tb + OFF_AH + row * ROWB + koff);
                if (p1) LDSM4(al[mi], tb + OFF_AL + row * ROWB + koff);
            }
#pragma unroll
            for (int ni = 0; ni < 8; ni++) {
                uint32_t n = wc * 64 + ni * 8 + bln;
                uint32_t ba = tb + OFF_B + n * ROWB + k16 * 32 + blc;
                uint32_t b0 = *(const uint32_t*)__cvta_shared_to_generic(ba);
                uint32_t b1 = *(const uint32_t*)__cvta_shared_to_generic(ba + 16);
                MMA16(acc[0][ni], ah[0], b0, b1);
                MMA16(acc[1][ni], ah[1], b0, b1);
                if (p1) {
                    MMA16(acc[0][ni], al[0], b0, b1);
                    MMA16(acc[1][ni], al[1], b0, b1);
                }
            }
        }
        __syncthreads();
        if (cc + 1 < 2 * NCH) {
            do_sts((cc + 1) & 1);
            __syncthreads();
        }
    }

    // ---- epilogue: decay + masked softmax over t, score = sum p*sim ------
    float* s_rmax = (float*)(smem + SM_TILES);          // [128][4]
    float* s_z    = (float*)(smem + SM_TILES + 2048);   // [128][4]
    float* s_s    = (float*)(smem + SM_TILES + 4096);   // [128][4]

    // stage 1: per-row max over this warp's 64 cols
#pragma unroll
    for (int mi = 0; mi < 2; mi++)
#pragma unroll
        for (int q8 = 0; q8 < 2; q8++) {
            int r = wr * 32 + mi * 16 + q8 * 8 + (lane >> 2);
            int sg = s0 + r;
            float m = NEG_HUGE;
#pragma unroll
            for (int ni = 0; ni < 8; ni++)
#pragma unroll
                for (int e = 0; e < 2; e++) {
                    int t = wc * 64 + ni * 8 + 2 * (lane & 3) + e;
                    float v = acc[mi][ni][q8 * 2 + e];
                    int d = sg - t; d = (d < 0) ? -d : d;
                    float l = v * s_wd[d];
                    if (s_kv[t] > 0.f) m = fmaxf(m, l);
                }
            m = fmaxf(m, __shfl_xor_sync(0xFFFFFFFFu, m, 1));
            m = fmaxf(m, __shfl_xor_sync(0xFFFFFFFFu, m, 2));
            if ((lane & 3) == 0) s_rmax[r * 4 + wc] = m;
        }
    __syncthreads();

    // stage 2: exp-sum and weighted sim-sum
#pragma unroll
    for (int mi = 0; mi < 2; mi++)
#pragma unroll
        for (int q8 = 0; q8 < 2; q8++) {
            int r = wr * 32 + mi * 16 + q8 * 8 + (lane >> 2);
            int sg = s0 + r;
            float M = fmaxf(fmaxf(s_rmax[r * 4], s_rmax[r * 4 + 1]),
                            fmaxf(s_rmax[r * 4 + 2], s_rmax[r * 4 + 3]));
            float Z = 0.f, S = 0.f;
#pragma unroll
            for (int ni = 0; ni < 8; ni++)
#pragma unroll
                for (int e = 0; e < 2; e++) {
                    int t = wc * 64 + ni * 8 + 2 * (lane & 3) + e;
                    float v = acc[mi][ni][q8 * 2 + e];
                    int d = sg - t; d = (d < 0) ? -d : d;
                    float l = v * s_wd[d];
                    float ex = (s_kv[t] > 0.f) ? __expf(l - M) : 0.f;
                    Z += ex; S += ex * v;
                }
            Z += __shfl_xor_sync(0xFFFFFFFFu, Z, 1);
            Z += __shfl_xor_sync(0xFFFFFFFFu, Z, 2);
            S += __shfl_xor_sync(0xFFFFFFFFu, S, 1);
            S += __shfl_xor_sync(0xFFFFFFFFu, S, 2);
            if ((lane & 3) == 0) { s_z[r * 4 + wc] = Z; s_s[r * 4 + wc] = S; }
        }
    __syncthreads();

    // stage 3: combine warp-cols, apply q_mask, block-reduce
    float val = 0.f;
    if (tid < 128) {
        int r = tid;
        float Z = s_z[r * 4] + s_z[r * 4 + 1] + s_z[r * 4 + 2] + s_z[r * 4 + 3];
        float S = s_s[r * 4] + s_s[r * 4 + 1] + s_s[r * 4 + 2] + s_s[r * 4 + 3];
        float sc = (Z > 0.f) ? (S / Z) : 0.f;
        val = sc * qmask[i * SEQ + s0 + r];
    }
#pragma unroll
    for (int o = 16; o > 0; o >>= 1) val += __shfl_xor_sync(0xFFFFFFFFu, val, o);
    if (tid < 128 && lane == 0) s_red[w] = val;
    __syncthreads();
    if (tid == 0) {
        float tot = s_red[0] + s_red[1] + s_red[2] + s_red[3];
        g_partial[bx] = tot;
    }
}

// ---------------------------------------------------------------------------
// Kernel 4: combine halves, apply 1/denom
// ---------------------------------------------------------------------------
__global__ void finalize_kernel(float* __restrict__ out) {
    int p = blockIdx.x * blockDim.x + threadIdx.x;
    if (p < BATCH * BATCH)
        out[p] = (g_partial[2 * p] + g_partial[2 * p + 1]) * g_invden[p >> 5];
}

// ---------------------------------------------------------------------------
extern "C" void kernel_launch(void* const* d_in, const int* in_sizes, int n_in,
                              void* d_out, int out_size) {
    const float* q  = (const float*)d_in[0];
    const float* k  = (const float*)d_in[1];
    const float* qm = (const float*)d_in[2];
    const float* km = (const float*)d_in[3];
    const float* ar = (const float*)d_in[4];
    const float* ls = (const float*)d_in[5];
    float* out = (float*)d_out;

    static int attr_done = 0;
    if (!attr_done) {
        cudaFuncSetAttribute(pair_kernel, cudaFuncAttributeMaxDynamicSharedMemorySize, SMEM_TOTAL);
        attr_done = 1;
    }

    norm_kernel<<<2 * BATCH * SEQ, 256>>>(q, k);
    tables_kernel<<<1, 256>>>(qm, ar, ls);
    pair_kernel<<<BATCH * BATCH * 2, NTP, SMEM_TOTAL>>>(qm, km);
    finalize_kernel<<<4, 256>>>(out);
}